// round 1
// baseline (speedup 1.0000x reference)
#include <cuda_runtime.h>
#include <cuda_bf16.h>
#include <math.h>

// Problem constants
#define T_LEN 2048
#define B_DIM 2
#define E_DIM 1024
#define H_NUM 16
#define HD 64
#define M_ROWS (T_LEN * B_DIM)       // 4096
#define E3 (3 * E_DIM)               // 3072
#define NHEADS (B_DIM * H_NUM)       // 32
#define OUT_ELEMS ((size_t)T_LEN * B_DIM * E_DIM)            // 4,194,304
#define P_ELEMS ((size_t)NHEADS * T_LEN * T_LEN)             // 134,217,728

// Scratch in device globals (no allocation allowed)
__device__ float g_qkv[(size_t)M_ROWS * E3];      // 48 MB: [4096, 3072]
__device__ float g_vt[(size_t)NHEADS * HD * T_LEN]; // 16 MB: [32][64][2048]
__device__ float g_attn[(size_t)M_ROWS * E_DIM];  // 16 MB: [4096, 1024]

// ---------------------------------------------------------------------------
// Generic NT GEMM tile: C[M,N] = scale * A[M,K] * B[N,K]^T + bias[N]
// Block tile 64x64, 16x16 threads, 4x4 micro-tile, K-step 16.
// All dims assumed multiples of tile sizes (true for this problem).
// ---------------------------------------------------------------------------
#define BM 64
#define BN 64
#define BK 16

__device__ __forceinline__ void gemm_nt_device(
    const float* __restrict__ A, int lda,
    const float* __restrict__ B, int ldb,
    float* __restrict__ C, int ldc,
    int K, float scale, const float* __restrict__ bias)
{
    __shared__ float As[BK][BM];
    __shared__ float Bs[BK][BN];

    const int tx = threadIdx.x;          // 0..15
    const int ty = threadIdx.y;          // 0..15
    const int tid = ty * 16 + tx;        // 0..255
    const int blockM = blockIdx.y * BM;
    const int blockN = blockIdx.x * BN;

    float acc[4][4] = {};

    const int lrow = tid >> 2;           // 0..63
    const int lk   = (tid & 3) * 4;      // 0,4,8,12

    const float* Arow = A + (size_t)(blockM + lrow) * lda + lk;
    const float* Brow = B + (size_t)(blockN + lrow) * ldb + lk;

    for (int k0 = 0; k0 < K; k0 += BK) {
        float4 av = *(const float4*)(Arow + k0);
        float4 bv = *(const float4*)(Brow + k0);
        __syncthreads();
        As[lk + 0][lrow] = av.x;
        As[lk + 1][lrow] = av.y;
        As[lk + 2][lrow] = av.z;
        As[lk + 3][lrow] = av.w;
        Bs[lk + 0][lrow] = bv.x;
        Bs[lk + 1][lrow] = bv.y;
        Bs[lk + 2][lrow] = bv.z;
        Bs[lk + 3][lrow] = bv.w;
        __syncthreads();

#pragma unroll
        for (int kk = 0; kk < BK; kk++) {
            float a0 = As[kk][ty * 4 + 0];
            float a1 = As[kk][ty * 4 + 1];
            float a2 = As[kk][ty * 4 + 2];
            float a3 = As[kk][ty * 4 + 3];
            float b0 = Bs[kk][tx * 4 + 0];
            float b1 = Bs[kk][tx * 4 + 1];
            float b2 = Bs[kk][tx * 4 + 2];
            float b3 = Bs[kk][tx * 4 + 3];
            acc[0][0] += a0 * b0; acc[0][1] += a0 * b1; acc[0][2] += a0 * b2; acc[0][3] += a0 * b3;
            acc[1][0] += a1 * b0; acc[1][1] += a1 * b1; acc[1][2] += a1 * b2; acc[1][3] += a1 * b3;
            acc[2][0] += a2 * b0; acc[2][1] += a2 * b1; acc[2][2] += a2 * b2; acc[2][3] += a2 * b3;
            acc[3][0] += a3 * b0; acc[3][1] += a3 * b1; acc[3][2] += a3 * b2; acc[3][3] += a3 * b3;
        }
    }

#pragma unroll
    for (int i = 0; i < 4; i++) {
        const int n0 = blockN + tx * 4;
        float* Crow = C + (size_t)(blockM + ty * 4 + i) * ldc + n0;
#pragma unroll
        for (int j = 0; j < 4; j++) {
            float v = acc[i][j] * scale;
            if (bias) v += bias[n0 + j];
            Crow[j] = v;
        }
    }
}

// ---------------------------------------------------------------------------
// Kernel wrappers
// ---------------------------------------------------------------------------

// qkv[4096,3072] = g[4096,1024] @ W_in[3072,1024]^T + b_in
__global__ void k_qkv(const float* __restrict__ g,
                      const float* __restrict__ Win,
                      const float* __restrict__ bin)
{
    gemm_nt_device(g, E_DIM, Win, E_DIM, g_qkv, E3, E_DIM, 1.0f, bin);
}

// Vt[bh][d][s] = qkv[s*B + b][2*E + h*64 + d]
__global__ void k_build_vt()
{
    size_t idx = (size_t)blockIdx.x * blockDim.x + threadIdx.x;
    int s = (int)(idx % T_LEN);
    int rest = (int)(idx / T_LEN);
    int d = rest % HD;
    int bh = rest / HD;
    int b = bh >> 4;           // bh / H_NUM
    int h = bh & 15;           // bh % H_NUM
    g_vt[idx] = g_qkv[(size_t)(s * B_DIM + b) * E3 + 2 * E_DIM + h * HD + d];
}

// S[bh][t][s] = scale * sum_d q[t,d] * k[s,d]   (written unsoftmaxed into P)
__global__ void k_scores(float* __restrict__ P)
{
    int bh = blockIdx.z;
    int b = bh >> 4;
    int h = bh & 15;
    const float* A = g_qkv + (size_t)b * E3 + h * HD;                 // q
    const float* Bm = g_qkv + (size_t)b * E3 + E_DIM + h * HD;        // k
    float* C = P + (size_t)bh * T_LEN * T_LEN;
    gemm_nt_device(A, B_DIM * E3, Bm, B_DIM * E3, C, T_LEN, HD, 0.125f, nullptr);
}

// Row softmax over rows of length 2048; one block per row.
__global__ void k_softmax(float* __restrict__ P)
{
    float* row = P + (size_t)blockIdx.x * T_LEN;
    const int tid = threadIdx.x;   // 256 threads
    float vals[8];
    float m = -INFINITY;
#pragma unroll
    for (int i = 0; i < 8; i++) {
        vals[i] = row[tid + i * 256];
        m = fmaxf(m, vals[i]);
    }
    // block max reduce
    __shared__ float red[32];
#pragma unroll
    for (int o = 16; o > 0; o >>= 1)
        m = fmaxf(m, __shfl_xor_sync(0xFFFFFFFFu, m, o));
    if ((tid & 31) == 0) red[tid >> 5] = m;
    __syncthreads();
    if (tid < 32) {
        float v = (tid < 8) ? red[tid] : -INFINITY;
#pragma unroll
        for (int o = 4; o > 0; o >>= 1)
            v = fmaxf(v, __shfl_xor_sync(0xFFFFFFFFu, v, o));
        if (tid == 0) red[0] = v;
    }
    __syncthreads();
    m = red[0];

    float sum = 0.0f;
#pragma unroll
    for (int i = 0; i < 8; i++) {
        vals[i] = expf(vals[i] - m);
        sum += vals[i];
    }
    __syncthreads();  // reuse red[]
#pragma unroll
    for (int o = 16; o > 0; o >>= 1)
        sum += __shfl_xor_sync(0xFFFFFFFFu, sum, o);
    if ((tid & 31) == 0) red[tid >> 5] = sum;
    __syncthreads();
    if (tid < 32) {
        float v = (tid < 8) ? red[tid] : 0.0f;
#pragma unroll
        for (int o = 4; o > 0; o >>= 1)
            v += __shfl_xor_sync(0xFFFFFFFFu, v, o);
        if (tid == 0) red[0] = v;
    }
    __syncthreads();
    float inv = 1.0f / red[0];
#pragma unroll
    for (int i = 0; i < 8; i++)
        row[tid + i * 256] = vals[i] * inv;
}

// attn[t, b, h*64+d] = sum_s P[bh][t][s] * Vt[bh][d][s]
__global__ void k_pv(const float* __restrict__ P)
{
    int bh = blockIdx.z;
    int b = bh >> 4;
    int h = bh & 15;
    const float* A = P + (size_t)bh * T_LEN * T_LEN;
    const float* Bm = g_vt + (size_t)bh * HD * T_LEN;
    float* C = g_attn + (size_t)b * E_DIM + h * HD;
    gemm_nt_device(A, T_LEN, Bm, T_LEN, C, B_DIM * E_DIM, T_LEN, 1.0f, nullptr);
}

// out[4096,1024] = attn[4096,1024] @ W_out[1024,1024]^T + b_out
__global__ void k_out(const float* __restrict__ Wout,
                      const float* __restrict__ bout,
                      float* __restrict__ out)
{
    gemm_nt_device(g_attn, E_DIM, Wout, E_DIM, out, E_DIM, E_DIM, 1.0f, bout);
}

// ---------------------------------------------------------------------------
extern "C" void kernel_launch(void* const* d_in, const int* in_sizes, int n_in,
                              void* d_out, int out_size)
{
    const float* g    = (const float*)d_in[0];
    const float* Win  = (const float*)d_in[1];
    const float* bin  = (const float*)d_in[2];
    const float* Wout = (const float*)d_in[3];
    const float* bout = (const float*)d_in[4];

    float* out = (float*)d_out;
    float* P   = (float*)d_out + OUT_ELEMS;   // attention probs go here

    dim3 blk(16, 16);

    // 1. QKV projection
    k_qkv<<<dim3(E3 / BN, M_ROWS / BM), blk>>>(g, Win, bin);

    // 2. V transpose for PV GEMM reuse
    k_build_vt<<<(int)((size_t)NHEADS * HD * T_LEN / 256), 256>>>();

    // 3. Scores (scaled, unsoftmaxed) straight into P region of d_out
    k_scores<<<dim3(T_LEN / BN, T_LEN / BM, NHEADS), blk>>>(P);

    // 4. Row softmax in place
    k_softmax<<<NHEADS * T_LEN, 256>>>(P);

    // 5. attn = P @ V
    k_pv<<<dim3(HD / BN, T_LEN / BM, NHEADS), blk>>>(P);

    // 6. Output projection
    k_out<<<dim3(E_DIM / BN, M_ROWS / BM), blk>>>(Wout, bout, out);
}

// round 2
// speedup vs baseline: 2.4707x; 2.4707x over previous
#include <cuda_runtime.h>
#include <cuda_bf16.h>
#include <math.h>
#include <stdint.h>

// Problem constants
#define T_LEN 2048
#define B_DIM 2
#define E_DIM 1024
#define H_NUM 16
#define HD 64
#define M_ROWS (T_LEN * B_DIM)       // 4096
#define E3 (3 * E_DIM)               // 3072
#define NHEADS (B_DIM * H_NUM)       // 32
#define OUT_ELEMS ((size_t)T_LEN * B_DIM * E_DIM)

// Scratch in device globals (no allocation allowed)
__device__ float g_qkv[(size_t)M_ROWS * E3];        // 48 MB
__device__ float g_vt[(size_t)NHEADS * HD * T_LEN]; // 16 MB
__device__ float g_attn[(size_t)M_ROWS * E_DIM];    // 16 MB

__device__ __forceinline__ uint32_t f2tf(float f) {
    uint32_t u;
    asm("cvt.rna.tf32.f32 %0, %1;" : "=r"(u) : "f"(f));
    return u;
}

__device__ __forceinline__ void mma_tf32(float c[4], const uint32_t a[4], const uint32_t b[2]) {
    asm volatile(
        "mma.sync.aligned.m16n8k8.row.col.f32.tf32.tf32.f32 "
        "{%0,%1,%2,%3}, {%4,%5,%6,%7}, {%8,%9}, {%0,%1,%2,%3};\n"
        : "+f"(c[0]), "+f"(c[1]), "+f"(c[2]), "+f"(c[3])
        : "r"(a[0]), "r"(a[1]), "r"(a[2]), "r"(a[3]), "r"(b[0]), "r"(b[1]));
}

// ---------------------------------------------------------------------------
// Tensor-core NT GEMM: C[M,N] = scale * A[M,K] @ B[N,K]^T + bias[N]
// BK=16, double-buffered smem, 256 threads, mma.m16n8k8.tf32.
// Requires: M % BM == 0, N % BN == 0, K % 16 == 0, 16B-aligned rows.
// ---------------------------------------------------------------------------
template <int BM, int BN, int WARPS_M, int WARPS_N>
__device__ __forceinline__ void gemm_tc(
    const float* __restrict__ A, int lda,
    const float* __restrict__ B, int ldb,
    float* __restrict__ C, int ldc,
    int K, float scale, const float* __restrict__ bias)
{
    constexpr int BK = 16;
    constexpr int LD = BK + 4;               // 20 floats: conflict-free frag loads
    constexpr int WTM = BM / WARPS_M;
    constexpr int WTN = BN / WARPS_N;
    constexpr int MT = WTM / 16;
    constexpr int NT = WTN / 8;
    constexpr int AR = (BM * (BK / 4)) / 256; // float4 loads/thread for A tile
    constexpr int BR = (BN * (BK / 4)) / 256;

    __shared__ uint32_t As[2][BM * LD];
    __shared__ uint32_t Bs[2][BN * LD];

    const int tid  = threadIdx.x;
    const int lane = tid & 31;
    const int warp = tid >> 5;
    const int wm = warp % WARPS_M;
    const int wn = warp / WARPS_M;
    const int g   = lane >> 2;   // groupID
    const int tig = lane & 3;    // threadID in group

    const int blockM = blockIdx.y * BM;
    const int blockN = blockIdx.x * BN;

    const float* Ab = A + (size_t)blockM * lda;
    const float* Bb = B + (size_t)blockN * ldb;

    float acc[MT][NT][4];
#pragma unroll
    for (int mi = 0; mi < MT; mi++)
#pragma unroll
        for (int ni = 0; ni < NT; ni++)
#pragma unroll
            for (int j = 0; j < 4; j++) acc[mi][ni][j] = 0.0f;

    float4 ar[AR], br[BR];

    auto load_tiles = [&](int k0) {
#pragma unroll
        for (int j = 0; j < AR; j++) {
            int i = tid + j * 256;
            int row = i >> 2, c = i & 3;
            ar[j] = *(const float4*)(Ab + (size_t)row * lda + k0 + c * 4);
        }
#pragma unroll
        for (int j = 0; j < BR; j++) {
            int i = tid + j * 256;
            int row = i >> 2, c = i & 3;
            br[j] = *(const float4*)(Bb + (size_t)row * ldb + k0 + c * 4);
        }
    };
    auto store_tiles = [&](int buf) {
#pragma unroll
        for (int j = 0; j < AR; j++) {
            int i = tid + j * 256;
            int row = i >> 2, c = i & 3;
            uint32_t* s = &As[buf][row * LD + c * 4];
            uint4 v = {f2tf(ar[j].x), f2tf(ar[j].y), f2tf(ar[j].z), f2tf(ar[j].w)};
            *(uint4*)s = v;
        }
#pragma unroll
        for (int j = 0; j < BR; j++) {
            int i = tid + j * 256;
            int row = i >> 2, c = i & 3;
            uint32_t* s = &Bs[buf][row * LD + c * 4];
            uint4 v = {f2tf(br[j].x), f2tf(br[j].y), f2tf(br[j].z), f2tf(br[j].w)};
            *(uint4*)s = v;
        }
    };
    auto compute = [&](int buf) {
#pragma unroll
        for (int ks = 0; ks < BK; ks += 8) {
            uint32_t af[MT][4];
            uint32_t bf[NT][2];
#pragma unroll
            for (int mi = 0; mi < MT; mi++) {
                int m = wm * WTM + mi * 16;
                const uint32_t* a = As[buf];
                af[mi][0] = a[(m + g) * LD + ks + tig];
                af[mi][1] = a[(m + g + 8) * LD + ks + tig];
                af[mi][2] = a[(m + g) * LD + ks + tig + 4];
                af[mi][3] = a[(m + g + 8) * LD + ks + tig + 4];
            }
#pragma unroll
            for (int ni = 0; ni < NT; ni++) {
                int n = wn * WTN + ni * 8;
                const uint32_t* b = Bs[buf];
                bf[ni][0] = b[(n + g) * LD + ks + tig];
                bf[ni][1] = b[(n + g) * LD + ks + tig + 4];
            }
#pragma unroll
            for (int mi = 0; mi < MT; mi++)
#pragma unroll
                for (int ni = 0; ni < NT; ni++)
                    mma_tf32(acc[mi][ni], af[mi], bf[ni]);
        }
    };

    const int nk = K / BK;
    load_tiles(0);
    store_tiles(0);
    __syncthreads();

    for (int it = 0; it < nk; it++) {
        int cur = it & 1;
        if (it + 1 < nk) load_tiles((it + 1) * BK);
        compute(cur);
        if (it + 1 < nk) {
            store_tiles(cur ^ 1);
            __syncthreads();
        }
    }

    // Epilogue
#pragma unroll
    for (int mi = 0; mi < MT; mi++) {
#pragma unroll
        for (int ni = 0; ni < NT; ni++) {
            int m0 = blockM + wm * WTM + mi * 16 + g;
            int n0 = blockN + wn * WTN + ni * 8 + 2 * tig;
            float b0 = bias ? bias[n0] : 0.0f;
            float b1 = bias ? bias[n0 + 1] : 0.0f;
            float2 v0 = {acc[mi][ni][0] * scale + b0, acc[mi][ni][1] * scale + b1};
            float2 v1 = {acc[mi][ni][2] * scale + b0, acc[mi][ni][3] * scale + b1};
            *(float2*)(C + (size_t)m0 * ldc + n0) = v0;
            *(float2*)(C + (size_t)(m0 + 8) * ldc + n0) = v1;
        }
    }
}

// ---------------------------------------------------------------------------
// Kernel wrappers
// ---------------------------------------------------------------------------

__global__ void k_qkv(const float* __restrict__ g,
                      const float* __restrict__ Win,
                      const float* __restrict__ bin)
{
    gemm_tc<128, 128, 2, 4>(g, E_DIM, Win, E_DIM, g_qkv, E3, E_DIM, 1.0f, bin);
}

__global__ void k_build_vt()
{
    size_t idx = (size_t)blockIdx.x * blockDim.x + threadIdx.x;
    int s = (int)(idx % T_LEN);
    int rest = (int)(idx / T_LEN);
    int d = rest % HD;
    int bh = rest / HD;
    int b = bh >> 4;
    int h = bh & 15;
    g_vt[idx] = g_qkv[(size_t)(s * B_DIM + b) * E3 + 2 * E_DIM + h * HD + d];
}

__global__ void k_scores(float* __restrict__ P)
{
    int bh = blockIdx.z;
    int b = bh >> 4;
    int h = bh & 15;
    const float* A  = g_qkv + (size_t)b * E3 + h * HD;           // q rows stride 6144
    const float* Bm = g_qkv + (size_t)b * E3 + E_DIM + h * HD;   // k
    float* C = P + (size_t)bh * T_LEN * T_LEN;
    gemm_tc<128, 128, 2, 4>(A, B_DIM * E3, Bm, B_DIM * E3, C, T_LEN, HD, 0.125f, nullptr);
}

__global__ void k_softmax(float* __restrict__ P)
{
    float* row = P + (size_t)blockIdx.x * T_LEN;
    const int tid = threadIdx.x;   // 256 threads
    float vals[8];
    float m = -INFINITY;
#pragma unroll
    for (int i = 0; i < 8; i++) {
        vals[i] = row[tid + i * 256];
        m = fmaxf(m, vals[i]);
    }
    __shared__ float red[32];
#pragma unroll
    for (int o = 16; o > 0; o >>= 1)
        m = fmaxf(m, __shfl_xor_sync(0xFFFFFFFFu, m, o));
    if ((tid & 31) == 0) red[tid >> 5] = m;
    __syncthreads();
    if (tid < 32) {
        float v = (tid < 8) ? red[tid] : -INFINITY;
#pragma unroll
        for (int o = 4; o > 0; o >>= 1)
            v = fmaxf(v, __shfl_xor_sync(0xFFFFFFFFu, v, o));
        if (tid == 0) red[0] = v;
    }
    __syncthreads();
    m = red[0];

    float sum = 0.0f;
#pragma unroll
    for (int i = 0; i < 8; i++) {
        vals[i] = expf(vals[i] - m);
        sum += vals[i];
    }
    __syncthreads();
#pragma unroll
    for (int o = 16; o > 0; o >>= 1)
        sum += __shfl_xor_sync(0xFFFFFFFFu, sum, o);
    if ((tid & 31) == 0) red[tid >> 5] = sum;
    __syncthreads();
    if (tid < 32) {
        float v = (tid < 8) ? red[tid] : 0.0f;
#pragma unroll
        for (int o = 4; o > 0; o >>= 1)
            v += __shfl_xor_sync(0xFFFFFFFFu, v, o);
        if (tid == 0) red[0] = v;
    }
    __syncthreads();
    float inv = 1.0f / red[0];
#pragma unroll
    for (int i = 0; i < 8; i++)
        row[tid + i * 256] = vals[i] * inv;
}

__global__ void k_pv(const float* __restrict__ P)
{
    int bh = blockIdx.z;
    int b = bh >> 4;
    int h = bh & 15;
    const float* A  = P + (size_t)bh * T_LEN * T_LEN;
    const float* Bm = g_vt + (size_t)bh * HD * T_LEN;
    float* C = g_attn + (size_t)b * E_DIM + h * HD;
    gemm_tc<128, 64, 4, 2>(A, T_LEN, Bm, T_LEN, C, B_DIM * E_DIM, T_LEN, 1.0f, nullptr);
}

__global__ void k_out(const float* __restrict__ Wout,
                      const float* __restrict__ bout,
                      float* __restrict__ out)
{
    gemm_tc<128, 128, 2, 4>(g_attn, E_DIM, Wout, E_DIM, out, E_DIM, E_DIM, 1.0f, bout);
}

// ---------------------------------------------------------------------------
extern "C" void kernel_launch(void* const* d_in, const int* in_sizes, int n_in,
                              void* d_out, int out_size)
{
    const float* g    = (const float*)d_in[0];
    const float* Win  = (const float*)d_in[1];
    const float* bin  = (const float*)d_in[2];
    const float* Wout = (const float*)d_in[3];
    const float* bout = (const float*)d_in[4];

    float* out = (float*)d_out;
    float* P   = (float*)d_out + OUT_ELEMS;

    // 1. QKV projection: [4096,3072] = [4096,1024] @ [3072,1024]^T
    k_qkv<<<dim3(E3 / 128, M_ROWS / 128), 256>>>(g, Win, bin);

    // 2. V transpose
    k_build_vt<<<(int)((size_t)NHEADS * HD * T_LEN / 256), 256>>>();

    // 3. Scores into P region
    k_scores<<<dim3(T_LEN / 128, T_LEN / 128, NHEADS), 256>>>(P);

    // 4. Row softmax in place
    k_softmax<<<NHEADS * T_LEN, 256>>>(P);

    // 5. attn = P @ V
    k_pv<<<dim3(1, T_LEN / 128, NHEADS), 256>>>(P);

    // 6. Output projection
    k_out<<<dim3(E_DIM / 128, M_ROWS / 128), 256>>>(Wout, bout, out);
}